// round 15
// baseline (speedup 1.0000x reference)
#include <cuda_runtime.h>
#include <stdint.h>
#include <math.h>

#define BB 512
#define SS 256
#define NUM_LOC 50000
#define NUM_USERS 10000
#define DD 256
#define NG 1024        // 4*D gate dim (gate-interleaved n' = 4*cell + gate)
#define NEGV -1000000000.0f

// ---------------- device scratch (no cudaMalloc allowed) ----------------
__device__ float g_locC[(size_t)NUM_LOC * NG];     // 204.8 MB (bias folded in)
__device__ float g_userC[(size_t)NUM_USERS * NG];  // 41 MB
__device__ float g_hourC[25 * NG];
__device__ float g_wdC[8 * NG];
__device__ float g_hwC[200 * NG];                  // combined hour*8+wd table
__device__ float g_biasr[NG];
__device__ float g_Whhr[NG * DD];                  // gate-interleaved W_hh
__device__ float g_h[2][BB * DD];                  // double-buffered hidden
__device__ float g_context[BB * DD];
__device__ int   g_seqlen[BB];
__device__ float g_hidden1[BB * DD];
__device__ float g_mix[BB];
__device__ int   g_recloc[BB * 5];
__device__ float g_recscore[BB * 5];
__device__ int   g_maskflag[1];
__device__ int4  g_idx[SS * BB];                   // per (t, b): loc, user, hr*8+wd
__device__ int   g_bar[SS * 16];                   // per-step, per-batch-group counters

typedef unsigned long long ull;
typedef unsigned int u32;
__device__ __forceinline__ void fma2(ull &d, ull a, ull b) {
    asm("fma.rn.f32x2 %0, %1, %2, %0;" : "+l"(d) : "l"(a), "l"(b));
}
__device__ __forceinline__ void add2(ull &d, ull a) {
    asm("add.rn.f32x2 %0, %0, %1;" : "+l"(d) : "l"(a));
}
__device__ __forceinline__ ull pk2(float x, float y) {
    ull r; asm("mov.b64 %0, {%1, %2};" : "=l"(r) : "f"(x), "f"(y)); return r;
}
__device__ __forceinline__ float2 upk(ull v) {
    float2 r; asm("mov.b64 {%0, %1}, %2;" : "=f"(r.x), "=f"(r.y) : "l"(v)); return r;
}
__device__ __forceinline__ void poll_cnt(const int* p) {
    int v;
    do {
        asm volatile("ld.acquire.gpu.global.b32 %0, [%1];" : "=r"(v) : "l"(p));
    } while (v < 8);
}

__device__ __forceinline__ float geluf(float x) {
    return 0.5f * x * (1.0f + erff(x * 0.70710678118654752f));
}
__device__ __forceinline__ float sigm(float x) { return 1.0f / (1.0f + __expf(-x)); }
__device__ __forceinline__ float tanh_(float x) {
    return 1.0f - 2.0f / (__expf(2.0f * x) + 1.0f);
}

// ---------------- mask dtype detection ----------------
__global__ void detect_mask(const unsigned char* mask) {
    __shared__ int s;
    if (threadIdx.x == 0) s = 0;
    __syncthreads();
    int f = 0;
    for (int i = threadIdx.x * 4 + 1; i < BB * SS; i += blockDim.x * 4)
        if (mask[i]) f = 1;
    if (f) atomicOr(&s, 1);
    __syncthreads();
    if (threadIdx.x == 0) g_maskflag[0] = s;
}

__global__ void seqlen_kernel(const void* mask) {
    int b = blockIdx.x * blockDim.x + threadIdx.x;
    if (b >= BB) return;
    int flag = g_maskflag[0];
    int cnt = 0;
    if (flag) {
        const unsigned char* m = (const unsigned char*)mask;
        for (int s = 0; s < SS; s++) cnt += (m[b * SS + s] != 0);
    } else {
        const int* m = (const int*)mask;
        for (int s = 0; s < SS; s++) cnt += (m[b * SS + s] != 0);
    }
    g_seqlen[b] = cnt - 1;
}

// gate-interleave W_hh and biases; zero barrier counters (every replay)
__global__ void reorder_kernel(const float* __restrict__ W_hh,
                               const float* __restrict__ b_ih,
                               const float* __restrict__ b_hh) {
    int np = blockIdx.x;                     // 0..1023
    int row = ((np & 3) << 8) + (np >> 2);
    g_Whhr[np * DD + threadIdx.x] = W_hh[row * DD + threadIdx.x];
    if (threadIdx.x == 0) g_biasr[np] = b_ih[row] + b_hh[row];
    if (np < 16) g_bar[np * 256 + threadIdx.x] = 0;
}

// transpose indices to [t][b] with hour/wd combined
__global__ void build_idx(const int* __restrict__ locs, const int* __restrict__ usrs,
                          const int* __restrict__ wds, const int* __restrict__ sms) {
    int t = blockIdx.x, b = threadIdx.x;     // grid SS, block 512
    int4 v;
    v.x = locs[b * SS + t];
    v.y = usrs[b * SS + t];
    int hr = sms[b * SS + t] / 60;
    if (hr > 24) hr = 24;
    v.z = hr * 8 + wds[b * SS + t];
    v.w = 0;
    g_idx[t * BB + b] = v;
}

// combined hour+weekday contribution table (after contrib GEMMs)
__global__ void build_hw() {
    int r = blockIdx.x;                      // 0..199
    int c = threadIdx.x * 4;                 // 256 threads
    float4 a = *(const float4*)&g_hourC[(r >> 3) * NG + c];
    float4 b = *(const float4*)&g_wdC[(r & 7) * NG + c];
    float4 o = make_float4(a.x + b.x, a.y + b.y, a.z + b.z, a.w + b.w);
    *(float4*)&g_hwC[r * NG + c] = o;
}

// ---------------- 128x128x8 double-buffered fp32x2 GEMM ----------------
__global__ void __launch_bounds__(256, 2)
gemm128(const float* __restrict__ A, int M, int lda,
        const float* __restrict__ W, int ldw, int k0, int K,
        int N, int mode, const float* __restrict__ bias2,
        float* __restrict__ out) {
    __shared__ float As[2][8][132];
    __shared__ float Ws[2][8][132];
    if (mode == 4) A = g_hidden1;

    const int m0 = blockIdx.x * 128;
    const int n0 = blockIdx.y * 128;
    const int tid = threadIdx.x;
    const int tx = tid & 15, ty = tid >> 4;

    const int lr = tid >> 1;
    const int lk = (tid & 1) * 4;

    const bool aok = (m0 + lr) < M;
    const float* ap = A + (size_t)(aok ? (m0 + lr) : 0) * lda + lk;
    int wn = n0 + lr;
    bool wok;
    const float* wp;
    if (mode < 4) {
        int wr = ((wn & 3) << 8) + (wn >> 2);
        wp = W + (size_t)wr * ldw + k0 + lk;
        wok = true;
    } else {
        wok = wn < N;
        wp = W + (size_t)(wok ? wn : 0) * ldw + lk;
    }

    ull acc[8][4];
#pragma unroll
    for (int r = 0; r < 8; r++)
#pragma unroll
        for (int p = 0; p < 4; p++) acc[r][p] = 0ULL;

    const float4 Z = make_float4(0.f, 0.f, 0.f, 0.f);
    const int nk = K >> 3;

    float4 va = aok ? *(const float4*)ap : Z;
    float4 vw = wok ? *(const float4*)wp : Z;
    As[0][lk + 0][lr] = va.x; As[0][lk + 1][lr] = va.y;
    As[0][lk + 2][lr] = va.z; As[0][lk + 3][lr] = va.w;
    Ws[0][lk + 0][lr] = vw.x; Ws[0][lk + 1][lr] = vw.y;
    Ws[0][lk + 2][lr] = vw.z; Ws[0][lk + 3][lr] = vw.w;
    __syncthreads();

    int cur = 0;
    for (int it = 0; it < nk; it++) {
        float4 vaN = Z, vwN = Z;
        if (it + 1 < nk) {
            if (aok) vaN = *(const float4*)(ap + (it + 1) * 8);
            if (wok) vwN = *(const float4*)(wp + (it + 1) * 8);
        }
#pragma unroll
        for (int k = 0; k < 8; k++) {
            float4 a0 = *(const float4*)&As[cur][k][ty * 4];
            float4 a1 = *(const float4*)&As[cur][k][64 + ty * 4];
            float4 w0 = *(const float4*)&Ws[cur][k][tx * 4];
            float4 w1 = *(const float4*)&Ws[cur][k][64 + tx * 4];
            ull W0 = pk2(w0.x, w0.y), W1 = pk2(w0.z, w0.w);
            ull W2 = pk2(w1.x, w1.y), W3 = pk2(w1.z, w1.w);
            float ar[8] = {a0.x, a0.y, a0.z, a0.w, a1.x, a1.y, a1.z, a1.w};
#pragma unroll
            for (int r = 0; r < 8; r++) {
                ull ad = pk2(ar[r], ar[r]);
                fma2(acc[r][0], ad, W0);
                fma2(acc[r][1], ad, W1);
                fma2(acc[r][2], ad, W2);
                fma2(acc[r][3], ad, W3);
            }
        }
        if (it + 1 < nk) {
            int nxt = cur ^ 1;
            As[nxt][lk + 0][lr] = vaN.x; As[nxt][lk + 1][lr] = vaN.y;
            As[nxt][lk + 2][lr] = vaN.z; As[nxt][lk + 3][lr] = vaN.w;
            Ws[nxt][lk + 0][lr] = vwN.x; Ws[nxt][lk + 1][lr] = vwN.y;
            Ws[nxt][lk + 2][lr] = vwN.z; Ws[nxt][lk + 3][lr] = vwN.w;
        }
        __syncthreads();
        cur ^= 1;
    }

    float* C = (mode == 0) ? g_locC : (mode == 1) ? g_userC
             : (mode == 2) ? g_hourC : (mode == 3) ? g_wdC : out;
#pragma unroll
    for (int hm = 0; hm < 2; hm++) {
#pragma unroll
        for (int i = 0; i < 4; i++) {
            int row = m0 + hm * 64 + ty * 4 + i;
            if (row >= M) continue;
            int ri = hm * 4 + i;
#pragma unroll
            for (int hn = 0; hn < 2; hn++) {
                int nb = n0 + hn * 64 + tx * 4;
                float2 p0 = upk(acc[ri][hn * 2 + 0]);
                float2 p1 = upk(acc[ri][hn * 2 + 1]);
                float4 v = make_float4(p0.x, p0.y, p1.x, p1.y);
                if (mode < 4) {
                    if (mode == 0) {
                        float4 bv = *(const float4*)&g_biasr[nb];
                        v.x += bv.x; v.y += bv.y; v.z += bv.z; v.w += bv.w;
                    }
                    *(float4*)&C[(size_t)row * NG + nb] = v;
                } else {
                    if (nb < N) {
                        float4 b2 = *(const float4*)&bias2[nb];
                        float mm = g_mix[row];
                        float om = 1.0f - mm;
                        float base = mm * NEGV;
                        float4 o;
                        o.x = base + om * (v.x + b2.x);
                        o.y = base + om * (v.y + b2.y);
                        o.z = base + om * (v.z + b2.z);
                        o.w = base + om * (v.w + b2.w);
                        *(float4*)&C[(size_t)row * NUM_LOC + nb] = o;
                    }
                }
            }
        }
    }
}

// ---------------- persistent LSTM v9: 512 threads, 4-way k-split -----------
// grid 128 CTAs. block (bi, ci): batch rows [bi*32,+32), gate cols [ci*128,+128).
// 16 warps = 4 batch groups x 4 k-quarters (64 k each). 4 warps/SMSP from
// independent chains hide LDS/L2/poll latency. 3 partial planes merged via
// padded SMEM with add.rn.f32x2.
#define WS_BYTES 131072
#define HS_BYTES (DD * 34 * 4)              // 34816
#define RED_OFF  (WS_BYTES + HS_BYTES)
#define SMEM_TOT (RED_OFF + 3 * 128 * 17 * 8)   // 218112

__global__ void __launch_bounds__(512, 1)
lstm_persistent() {
    extern __shared__ char smraw[];
    float* ws = (float*)smraw;                       // [256 k][128 local cols]
    float* hs = (float*)(smraw + WS_BYTES);          // [256 k][34]
    ull*   red = (ull*)(smraw + RED_OFF);            // [3][128 thr][17]

    const int tid = threadIdx.x;
    const int bi = blockIdx.x & 15;
    const int ci = blockIdx.x >> 4;
    const int b0 = bi * 32;
    const int n0 = ci * 128;
    const int wid = tid >> 5;                        // 0..15
    const int lane = tid & 31;                       // cell within slice
    const int wrp = wid & 3;                         // batch group
    const int kq = wid >> 2;                         // k quarter 0..3
    const int bwl = wrp * 8;                         // local batch base
    const int bw = b0 + bwl;                         // global batch base
    const int g0 = n0 + lane * 4;                    // global gate col base
    const int cellG = ci * 32 + lane;                // global cell index (k)
    const int st_r = tid & 31;                       // staging batch row
    const int st_q = tid >> 5;                       // staging k-quad 0..15
    const int rt = tid & 127;                        // thread within kq plane

    // stage W slice: ws[k][c] = Whhr[(n0+c)][k]   (conflict-free)
    for (int i = tid; i < 8192; i += 512) {
        int c = i & 127, kqd = (i >> 7) << 2;
        float4 v = *(const float4*)&g_Whhr[(n0 + c) * DD + kqd];
        ws[(kqd + 0) * 128 + c] = v.x;
        ws[(kqd + 1) * 128 + c] = v.y;
        ws[(kqd + 2) * 128 + c] = v.z;
        ws[(kqd + 3) * 128 + c] = v.w;
    }

    int sl[8];
    float cst[8];
#pragma unroll
    for (int j = 0; j < 8; j++) {
        sl[j] = g_seqlen[bw + j];
        cst[j] = 0.0f;
    }

    // gather t = 0 (kq==0 warps only; others carry zero G)
    ull Gp[16];
#pragma unroll
    for (int i = 0; i < 16; i++) Gp[i] = 0ULL;
    if (kq == 0) {
        float gv[2][4];
#pragma unroll
        for (int bp = 0; bp < 4; bp++) {
#pragma unroll
            for (int e = 0; e < 2; e++) {
                int b = bw + bp * 2 + e;
                int4 id = __ldg(&g_idx[b]);
                float4 v1 = *(const float4*)&g_locC[(size_t)id.x * NG + g0];
                float4 v2 = *(const float4*)&g_userC[(size_t)id.y * NG + g0];
                float4 v3 = *(const float4*)&g_hwC[(size_t)id.z * NG + g0];
                gv[e][0] = v1.x + v2.x + v3.x;
                gv[e][1] = v1.y + v2.y + v3.y;
                gv[e][2] = v1.z + v2.z + v3.z;
                gv[e][3] = v1.w + v2.w + v3.w;
            }
#pragma unroll
            for (int g = 0; g < 4; g++)
                Gp[bp * 4 + g] = pk2(gv[0][g], gv[1][g]);
        }
    }
    __syncthreads();   // ws ready

    for (int t = 0; t < SS; t++) {
        ull acc[16];
#pragma unroll
        for (int i = 0; i < 16; i++) acc[i] = Gp[i];

        if (t > 0) {
            // all threads acquire-poll the producer counter (count reaches 8)
            poll_cnt(&g_bar[(t - 1) * 16 + bi]);
            // stage h: 512 threads, each 4 float4 loads + transpose STS
            const float* hsrc = g_h[t & 1] + (size_t)(b0 + st_r) * DD;
#pragma unroll
            for (int it = 0; it < 4; it++) {
                int k4 = (st_q + it * 16) << 2;
                float4 v = __ldcg((const float4*)(hsrc + k4));
                hs[(k4 + 0) * 34 + st_r] = v.x;
                hs[(k4 + 1) * 34 + st_r] = v.y;
                hs[(k4 + 2) * 34 + st_r] = v.z;
                hs[(k4 + 3) * 34 + st_r] = v.w;
            }
            __syncthreads();

            // inner loop: this warp's k quarter (64 k)
            const float* wp = ws + lane * 4 + (kq << 13);   // kq*64*128
            const float* hb = hs + bwl + kq * 64 * 34;
#pragma unroll 4
            for (int kk = 0; kk < 64; kk++) {
                float4 w4 = *(const float4*)(wp + (kk << 7));
                ull W0 = pk2(w4.x, w4.x), W1 = pk2(w4.y, w4.y);
                ull W2 = pk2(w4.z, w4.z), W3 = pk2(w4.w, w4.w);
                const ull* hk = (const ull*)(hb + kk * 34);
                ull h0 = hk[0], h1 = hk[1], h2 = hk[2], h3 = hk[3];
                fma2(acc[0], h0, W0);  fma2(acc[1], h0, W1);
                fma2(acc[2], h0, W2);  fma2(acc[3], h0, W3);
                fma2(acc[4], h1, W0);  fma2(acc[5], h1, W1);
                fma2(acc[6], h1, W2);  fma2(acc[7], h1, W3);
                fma2(acc[8], h2, W0);  fma2(acc[9], h2, W1);
                fma2(acc[10], h2, W2); fma2(acc[11], h2, W3);
                fma2(acc[12], h3, W0); fma2(acc[13], h3, W1);
                fma2(acc[14], h3, W2); fma2(acc[15], h3, W3);
            }

            // merge k-quarters: kq 1-3 store, kq 0 adds
            if (kq > 0) {
                ull* d = red + ((size_t)(kq - 1) * 128 + rt) * 17;
#pragma unroll
                for (int i = 0; i < 16; i++) d[i] = acc[i];
            }
            __syncthreads();
            if (kq == 0) {
#pragma unroll
                for (int p = 0; p < 3; p++) {
                    const ull* s = red + ((size_t)p * 128 + rt) * 17;
#pragma unroll
                    for (int i = 0; i < 16; i++) add2(acc[i], s[i]);
                }
            }
        }

        // pointwise: kq==0 warps, 8 batches x 1 cell per lane
        if (kq == 0) {
            float hn[8];
#pragma unroll
            for (int bp = 0; bp < 4; bp++) {
                float2 gi = upk(acc[bp * 4 + 0]);
                float2 gf = upk(acc[bp * 4 + 1]);
                float2 gg = upk(acc[bp * 4 + 2]);
                float2 go = upk(acc[bp * 4 + 3]);
                int b0e = bp * 2, b1e = bp * 2 + 1;
                float cn0 = sigm(gf.x) * cst[b0e] + sigm(gi.x) * tanh_(gg.x);
                hn[b0e] = sigm(go.x) * tanh_(cn0);
                cst[b0e] = cn0;
                float cn1 = sigm(gf.y) * cst[b1e] + sigm(gi.y) * tanh_(gg.y);
                hn[b1e] = sigm(go.y) * tanh_(cn1);
                cst[b1e] = cn1;
                if (t == sl[b0e]) g_context[(bw + b0e) * DD + cellG] = hn[b0e];
                if (t == sl[b1e]) g_context[(bw + b1e) * DD + cellG] = hn[b1e];
            }
            if (t < SS - 1) {
                float* h_out = g_h[(t + 1) & 1];
#pragma unroll
                for (int j = 0; j < 8; j++)
                    __stcg(&h_out[(bw + j) * DD + cellG], hn[j]);
            }
        }

        if (t < SS - 1) {
            __threadfence();
            __syncthreads();
            if (tid == 0) atomicAdd(&g_bar[t * 16 + bi], 1);

            // prefetch next step's gather (kq==0; overlaps peers)
            if (kq == 0) {
                float gv[2][4];
#pragma unroll
                for (int bp = 0; bp < 4; bp++) {
#pragma unroll
                    for (int e = 0; e < 2; e++) {
                        int b = bw + bp * 2 + e;
                        int4 id = __ldg(&g_idx[(t + 1) * BB + b]);
                        float4 v1 = *(const float4*)&g_locC[(size_t)id.x * NG + g0];
                        float4 v2 = *(const float4*)&g_userC[(size_t)id.y * NG + g0];
                        float4 v3 = *(const float4*)&g_hwC[(size_t)id.z * NG + g0];
                        gv[e][0] = v1.x + v2.x + v3.x;
                        gv[e][1] = v1.y + v2.y + v3.y;
                        gv[e][2] = v1.z + v2.z + v3.z;
                        gv[e][3] = v1.w + v2.w + v3.w;
                    }
#pragma unroll
                    for (int g = 0; g < 4; g++)
                        Gp[bp * 4 + g] = pk2(gv[0][g], gv[1][g]);
                }
            }
        }
    }
}

// ---------------- context MLP: hidden1 = gelu(ctx @ np_W1^T + b1); mix ------
__global__ void ctx_mlp(const float* __restrict__ np_W1, const float* __restrict__ np_b1,
                        const float* __restrict__ mx_W, const float* __restrict__ mx_b) {
    int b = blockIdx.x, tid = threadIdx.x;
    __shared__ float ctx[DD];
    __shared__ float red[DD];
    ctx[tid] = g_context[b * DD + tid];
    __syncthreads();
    float accv = np_b1[tid];
    const float* w = np_W1 + (size_t)tid * DD;
#pragma unroll 4
    for (int k = 0; k < DD; k++) accv += ctx[k] * w[k];
    g_hidden1[b * DD + tid] = geluf(accv);

    red[tid] = ctx[tid] * mx_W[tid];
    __syncthreads();
    for (int off = 128; off > 0; off >>= 1) {
        if (tid < off) red[tid] += red[tid + off];
        __syncthreads();
    }
    if (tid == 0) g_mix[b] = 1.0f / (1.0f + expf(-(red[0] + mx_b[0]))) * 0.9f + 0.05f;
}

// ---------------- recent-location scoring + dedup ----------------
__global__ void recent_kernel(const int* __restrict__ locations,
                              const int* __restrict__ start_mins,
                              const float* __restrict__ loc_table,
                              const float* __restrict__ sc_W1,
                              const float* __restrict__ sc_b1,
                              const float* __restrict__ sc_W2,
                              const float* __restrict__ sc_b2) {
    int b = blockIdx.x, tid = threadIdx.x;   // 128 threads
    __shared__ int rloc[5];
    __shared__ float td[5];
    __shared__ int val[5];
    __shared__ float hid[5][128];
    if (tid < 5) {
        int sl = g_seqlen[b];
        int idx = sl - tid;
        val[tid] = (idx >= 0);
        int ic = idx < 0 ? 0 : idx;
        rloc[tid] = locations[b * SS + ic];
        int ct = start_mins[b * SS + sl];
        td[tid] = (float)(ct - start_mins[b * SS + ic]) / 1440.0f;
    }
    __syncthreads();
    for (int j = 0; j < 5; j++) {
        const float* lt = loc_table + (size_t)rloc[j] * DD;
        const float* w = sc_W1 + (size_t)tid * 258;
        float a = sc_b1[tid] + td[j] * w[256] + (float)j * w[257];
#pragma unroll 4
        for (int k = 0; k < DD; k++) a += lt[k] * w[k];
        hid[j][tid] = geluf(a);
    }
    __syncthreads();
    if (tid < 5) {
        float sc = sc_b2[0];
        for (int k = 0; k < 128; k++) sc += hid[tid][k] * sc_W2[k];
        int keep = val[tid];
        for (int jp = 0; jp < tid; jp++)
            if (val[jp] && rloc[jp] == rloc[tid]) keep = 0;
        g_recloc[b * 5 + tid] = keep ? rloc[tid] : -1;
        g_recscore[b * 5 + tid] = sc;
    }
}

// ---------------- fixup: overwrite kept recent locations ----------------
__global__ void fixup_kernel(const float* __restrict__ np_W2,
                             const float* __restrict__ np_b2,
                             float* __restrict__ out) {
    int b = blockIdx.x, tid = threadIdx.x;   // 256 threads
    __shared__ float h1[DD];
    __shared__ float red[DD];
    h1[tid] = g_hidden1[b * DD + tid];
    __syncthreads();
    float mm = g_mix[b];
    for (int j = 0; j < 5; j++) {
        int l = g_recloc[b * 5 + j];
        if (l < 0) continue;
        red[tid] = h1[tid] * np_W2[(size_t)l * DD + tid];
        __syncthreads();
        for (int off = 128; off > 0; off >>= 1) {
            if (tid < off) red[tid] += red[tid + off];
            __syncthreads();
        }
        if (tid == 0)
            out[(size_t)b * NUM_LOC + l] =
                mm * g_recscore[b * 5 + j] + (1.0f - mm) * (red[0] + np_b2[l]);
        __syncthreads();
    }
}

// ---------------- launch ----------------
extern "C" void kernel_launch(void* const* d_in, const int* in_sizes, int n_in,
                              void* d_out, int out_size) {
    const int* locations   = (const int*)d_in[0];
    const int* users       = (const int*)d_in[1];
    const int* weekdays    = (const int*)d_in[2];
    const int* start_mins  = (const int*)d_in[3];
    const void* mask       = d_in[4];
    const float* loc_table  = (const float*)d_in[5];
    const float* user_table = (const float*)d_in[6];
    const float* hour_table = (const float*)d_in[7];
    const float* wd_table   = (const float*)d_in[8];
    const float* W_ih = (const float*)d_in[9];
    const float* W_hh = (const float*)d_in[10];
    const float* b_ih = (const float*)d_in[11];
    const float* b_hh = (const float*)d_in[12];
    const float* sc_W1 = (const float*)d_in[13];
    const float* sc_b1 = (const float*)d_in[14];
    const float* sc_W2 = (const float*)d_in[15];
    const float* sc_b2 = (const float*)d_in[16];
    const float* np_W1 = (const float*)d_in[17];
    const float* np_b1 = (const float*)d_in[18];
    const float* np_W2 = (const float*)d_in[19];
    const float* np_b2 = (const float*)d_in[20];
    const float* mx_W = (const float*)d_in[21];
    const float* mx_b = (const float*)d_in[22];
    float* out = (float*)d_out;

    detect_mask<<<1, 256>>>((const unsigned char*)mask);
    seqlen_kernel<<<2, 256>>>(mask);
    reorder_kernel<<<1024, 256>>>(W_hh, b_ih, b_hh);
    build_idx<<<SS, 512>>>(locations, users, weekdays, start_mins);

    gemm128<<<dim3(391, 8), 256>>>(loc_table, NUM_LOC, 256, W_ih, 448, 0, 256, NG, 0, nullptr, nullptr);
    gemm128<<<dim3(79, 8), 256>>>(user_table, NUM_USERS, 64, W_ih, 448, 256, 64, NG, 1, nullptr, nullptr);
    gemm128<<<dim3(1, 8), 256>>>(hour_table, 25, 64, W_ih, 448, 320, 64, NG, 2, nullptr, nullptr);
    gemm128<<<dim3(1, 8), 256>>>(wd_table, 8, 64, W_ih, 448, 384, 64, NG, 3, nullptr, nullptr);
    build_hw<<<200, 256>>>();

    cudaFuncSetAttribute(lstm_persistent, cudaFuncAttributeMaxDynamicSharedMemorySize, SMEM_TOT);
    lstm_persistent<<<128, 512, SMEM_TOT>>>();

    ctx_mlp<<<512, 256>>>(np_W1, np_b1, mx_W, mx_b);
    recent_kernel<<<512, 128>>>(locations, start_mins, loc_table,
                                sc_W1, sc_b1, sc_W2, sc_b2);
    gemm128<<<dim3(4, 391), 256>>>(nullptr, BB, 256, np_W2, 256, 0, 256, NUM_LOC, 4, np_b2, out);
    fixup_kernel<<<512, 256>>>(np_W2, np_b2, out);
}

// round 16
// speedup vs baseline: 1.1663x; 1.1663x over previous
#include <cuda_runtime.h>
#include <stdint.h>
#include <math.h>

#define BB 512
#define SS 256
#define NUM_LOC 50000
#define NUM_USERS 10000
#define DD 256
#define NG 1024        // 4*D gate dim (gate-interleaved n' = 4*cell + gate)
#define NEGV -1000000000.0f

// ---------------- device scratch (no cudaMalloc allowed) ----------------
__device__ float g_locC[(size_t)NUM_LOC * NG];     // 204.8 MB (bias folded in)
__device__ float g_userC[(size_t)NUM_USERS * NG];  // 41 MB
__device__ float g_hourC[25 * NG];
__device__ float g_wdC[8 * NG];
__device__ float g_hwC[200 * NG];                  // combined hour*8+wd table
__device__ float g_biasr[NG];
__device__ float g_Whhr[NG * DD];                  // gate-interleaved W_hh
__device__ float g_h[2][BB * DD];                  // double-buffered hidden
__device__ float g_context[BB * DD];
__device__ int   g_seqlen[BB];
__device__ float g_hidden1[BB * DD];
__device__ float g_mix[BB];
__device__ int   g_recloc[BB * 5];
__device__ float g_recscore[BB * 5];
__device__ int   g_maskflag[1];
__device__ int4  g_idx[SS * BB];                   // per (t, b): loc, user, hr*8+wd
__device__ int   g_bar[SS * 16];                   // per-step, per-batch-group counters

typedef unsigned long long ull;
typedef unsigned int u32;
__device__ __forceinline__ void fma2(ull &d, ull a, ull b) {
    asm("fma.rn.f32x2 %0, %1, %2, %0;" : "+l"(d) : "l"(a), "l"(b));
}
__device__ __forceinline__ void add2(ull &d, ull a) {
    asm("add.rn.f32x2 %0, %0, %1;" : "+l"(d) : "l"(a));
}
__device__ __forceinline__ ull pk2(float x, float y) {
    ull r; asm("mov.b64 %0, {%1, %2};" : "=l"(r) : "f"(x), "f"(y)); return r;
}
__device__ __forceinline__ float2 upk(ull v) {
    float2 r; asm("mov.b64 {%0, %1}, %2;" : "=f"(r.x), "=f"(r.y) : "l"(v)); return r;
}
__device__ __forceinline__ void poll_cnt(const int* p) {
    int v;
    do {
        asm volatile("ld.acquire.gpu.global.b32 %0, [%1];" : "=r"(v) : "l"(p));
    } while (v < 8);
}
__device__ __forceinline__ u32 tf32c(float x) {
    u32 r; asm("cvt.rna.tf32.f32 %0, %1;" : "=r"(r) : "f"(x)); return r;
}
#define MMA_TF32(d, a, b) \
    asm("mma.sync.aligned.m16n8k8.row.col.f32.tf32.tf32.f32 " \
        "{%0,%1,%2,%3}, {%4,%5,%6,%7}, {%8,%9}, {%0,%1,%2,%3};" \
        : "+f"((d)[0]), "+f"((d)[1]), "+f"((d)[2]), "+f"((d)[3]) \
        : "r"((a)[0]), "r"((a)[1]), "r"((a)[2]), "r"((a)[3]), \
          "r"((b)[0]), "r"((b)[1]))

__device__ __forceinline__ float geluf(float x) {
    return 0.5f * x * (1.0f + erff(x * 0.70710678118654752f));
}
__device__ __forceinline__ float sigm(float x) { return 1.0f / (1.0f + __expf(-x)); }
__device__ __forceinline__ float tanh_(float x) {
    return 1.0f - 2.0f / (__expf(2.0f * x) + 1.0f);
}

// ---------------- mask dtype detection ----------------
__global__ void detect_mask(const unsigned char* mask) {
    __shared__ int s;
    if (threadIdx.x == 0) s = 0;
    __syncthreads();
    int f = 0;
    for (int i = threadIdx.x * 4 + 1; i < BB * SS; i += blockDim.x * 4)
        if (mask[i]) f = 1;
    if (f) atomicOr(&s, 1);
    __syncthreads();
    if (threadIdx.x == 0) g_maskflag[0] = s;
}

__global__ void seqlen_kernel(const void* mask) {
    int b = blockIdx.x * blockDim.x + threadIdx.x;
    if (b >= BB) return;
    int flag = g_maskflag[0];
    int cnt = 0;
    if (flag) {
        const unsigned char* m = (const unsigned char*)mask;
        for (int s = 0; s < SS; s++) cnt += (m[b * SS + s] != 0);
    } else {
        const int* m = (const int*)mask;
        for (int s = 0; s < SS; s++) cnt += (m[b * SS + s] != 0);
    }
    g_seqlen[b] = cnt - 1;
}

// gate-interleave W_hh and biases; zero barrier counters (every replay)
__global__ void reorder_kernel(const float* __restrict__ W_hh,
                               const float* __restrict__ b_ih,
                               const float* __restrict__ b_hh) {
    int np = blockIdx.x;                     // 0..1023
    int row = ((np & 3) << 8) + (np >> 2);
    g_Whhr[np * DD + threadIdx.x] = W_hh[row * DD + threadIdx.x];
    if (threadIdx.x == 0) g_biasr[np] = b_ih[row] + b_hh[row];
    if (np < 16) g_bar[np * 256 + threadIdx.x] = 0;
}

// transpose indices to [t][b] with hour/wd combined
__global__ void build_idx(const int* __restrict__ locs, const int* __restrict__ usrs,
                          const int* __restrict__ wds, const int* __restrict__ sms) {
    int t = blockIdx.x, b = threadIdx.x;     // grid SS, block 512
    int4 v;
    v.x = locs[b * SS + t];
    v.y = usrs[b * SS + t];
    int hr = sms[b * SS + t] / 60;
    if (hr > 24) hr = 24;
    v.z = hr * 8 + wds[b * SS + t];
    v.w = 0;
    g_idx[t * BB + b] = v;
}

// combined hour+weekday contribution table (after contrib GEMMs)
__global__ void build_hw() {
    int r = blockIdx.x;                      // 0..199
    int c = threadIdx.x * 4;                 // 256 threads
    float4 a = *(const float4*)&g_hourC[(r >> 3) * NG + c];
    float4 b = *(const float4*)&g_wdC[(r & 7) * NG + c];
    float4 o = make_float4(a.x + b.x, a.y + b.y, a.z + b.z, a.w + b.w);
    *(float4*)&g_hwC[r * NG + c] = o;
}

// ---------------- tf32 tensor-core GEMM: 128x128 tile, 8 warps (2x4) -------
// C[m,n] = sum_k A[m,k] * W[rowmap(n), k0+k]
// mode 0/1: contrib tables (interleaved rowmap; mode 0 adds bias)
// mode 4:   vocab logits with blend epilogue (A = g_hidden1, W = np_W2)
__global__ void __launch_bounds__(256, 2)
gemm_tf32(const float* __restrict__ A, int M, int lda,
          const float* __restrict__ W, int ldw, int k0, int K,
          int N, int mode, const float* __restrict__ bias2,
          float* __restrict__ out) {
    __shared__ u32 As[32][136];
    __shared__ u32 Ws[32][136];
    if (mode == 4) A = g_hidden1;

    const int m0 = blockIdx.x * 128;
    const int n0 = blockIdx.y * 128;
    const int tid = threadIdx.x;
    const int wid = tid >> 5, lane = tid & 31;
    const int g = lane >> 2, tq = lane & 3;
    const int wm = wid >> 2, wn = wid & 3;       // warps 2 (m) x 4 (n)
    const int mb = wm * 64, nb = wn * 32;

    const int sr = tid >> 1;                     // staging row 0..127
    const int sk = (tid & 1) * 16;               // staging k half

    const bool aok = (m0 + sr) < M;
    const float* ap = A + (size_t)(aok ? (m0 + sr) : 0) * lda;
    int wcol = n0 + sr;
    bool wok;
    const float* wp;
    if (mode < 4) {
        int wr = ((wcol & 3) << 8) + (wcol >> 2);
        wp = W + (size_t)wr * ldw + k0;
        wok = true;
    } else {
        wok = wcol < N;
        wp = W + (size_t)(wok ? wcol : 0) * ldw;
    }

    float acc[4][4][4];                          // [mt][nt][c0..c3]
#pragma unroll
    for (int mt = 0; mt < 4; mt++)
#pragma unroll
        for (int nt = 0; nt < 4; nt++)
#pragma unroll
            for (int c = 0; c < 4; c++) acc[mt][nt][c] = 0.0f;

    const float4 Z = make_float4(0.f, 0.f, 0.f, 0.f);

    for (int kk = 0; kk < K; kk += 32) {
#pragma unroll
        for (int i = 0; i < 4; i++) {
            float4 va = aok ? *(const float4*)(ap + kk + sk + i * 4) : Z;
            float4 vw = wok ? *(const float4*)(wp + kk + sk + i * 4) : Z;
            int kb = sk + i * 4;
            As[kb + 0][sr] = tf32c(va.x);
            As[kb + 1][sr] = tf32c(va.y);
            As[kb + 2][sr] = tf32c(va.z);
            As[kb + 3][sr] = tf32c(va.w);
            Ws[kb + 0][sr] = tf32c(vw.x);
            Ws[kb + 1][sr] = tf32c(vw.y);
            Ws[kb + 2][sr] = tf32c(vw.z);
            Ws[kb + 3][sr] = tf32c(vw.w);
        }
        __syncthreads();

#pragma unroll
        for (int kt = 0; kt < 4; kt++) {
            u32 a[4][4], b[4][2];
            const int kA = kt * 8 + tq;
#pragma unroll
            for (int mt = 0; mt < 4; mt++) {
                int mr = mb + mt * 16 + g;
                a[mt][0] = As[kA][mr];
                a[mt][1] = As[kA][mr + 8];
                a[mt][2] = As[kA + 4][mr];
                a[mt][3] = As[kA + 4][mr + 8];
            }
#pragma unroll
            for (int nt = 0; nt < 4; nt++) {
                int nc = nb + nt * 8 + g;
                b[nt][0] = Ws[kA][nc];
                b[nt][1] = Ws[kA + 4][nc];
            }
#pragma unroll
            for (int mt = 0; mt < 4; mt++)
#pragma unroll
                for (int nt = 0; nt < 4; nt++)
                    MMA_TF32(acc[mt][nt], a[mt], b[nt]);
        }
        __syncthreads();
    }

    // epilogue
    float* C = (mode == 0) ? g_locC : (mode == 1) ? g_userC : out;
#pragma unroll
    for (int mt = 0; mt < 4; mt++) {
        int row0 = m0 + mb + mt * 16 + g;
        int row1 = row0 + 8;
#pragma unroll
        for (int nt = 0; nt < 4; nt++) {
            int col = n0 + nb + nt * 8 + 2 * tq;
            if (mode < 4) {
                float bx = 0.f, by = 0.f;
                if (mode == 0) {
                    float2 bv = *(const float2*)&g_biasr[col];
                    bx = bv.x; by = bv.y;
                }
                if (row0 < M)
                    *(float2*)&C[(size_t)row0 * NG + col] =
                        make_float2(acc[mt][nt][0] + bx, acc[mt][nt][1] + by);
                if (row1 < M)
                    *(float2*)&C[(size_t)row1 * NG + col] =
                        make_float2(acc[mt][nt][2] + bx, acc[mt][nt][3] + by);
            } else {
                if (col < N) {
                    float2 b2 = *(const float2*)&bias2[col];
                    if (row0 < M) {
                        float mm = g_mix[row0];
                        float om = 1.0f - mm, base = mm * NEGV;
                        *(float2*)&C[(size_t)row0 * NUM_LOC + col] =
                            make_float2(base + om * (acc[mt][nt][0] + b2.x),
                                        base + om * (acc[mt][nt][1] + b2.y));
                    }
                    if (row1 < M) {
                        float mm = g_mix[row1];
                        float om = 1.0f - mm, base = mm * NEGV;
                        *(float2*)&C[(size_t)row1 * NUM_LOC + col] =
                            make_float2(base + om * (acc[mt][nt][2] + b2.x),
                                        base + om * (acc[mt][nt][3] + b2.y));
                    }
                }
            }
        }
    }
}

// ---------------- small fp32 GEMM for hour/wd tables (modes 2,3) -----------
__global__ void __launch_bounds__(256)
gemm_small(const float* __restrict__ A, int M, int lda,
           const float* __restrict__ W, int ldw, int k0, int K, int mode) {
    // one block per 128 output cols; M <= 25
    float* C = (mode == 2) ? g_hourC : g_wdC;
    const int n0 = blockIdx.y * 128;
    const int tid = threadIdx.x;
    const int nl = tid >> 1;                 // 0..127 col
    const int mh = tid & 1;                  // row half
    int wn = n0 + nl;
    int wr = ((wn & 3) << 8) + (wn >> 2);
    const float* wp = W + (size_t)wr * ldw + k0;
    for (int m = mh; m < M; m += 2) {
        float s = 0.f;
        const float* arow = A + (size_t)m * lda;
        for (int k = 0; k < K; k++) s += arow[k] * wp[k];
        C[(size_t)m * NG + n0 + nl] = s;
    }
}

// ---------------- persistent LSTM (R11 proven): 256 thr, 2-way k-split -----
#define WS_BYTES 131072
#define HS_BYTES (DD * 34 * 4)              // 34816
#define RED_OFF  (WS_BYTES + HS_BYTES)
#define LSTM_SMEM (RED_OFF + 128 * 17 * 8)  // 183296

__global__ void __launch_bounds__(256, 1)
lstm_persistent() {
    extern __shared__ char smraw[];
    float* ws = (float*)smraw;                       // [256 k][128 local cols]
    float* hs = (float*)(smraw + WS_BYTES);          // [256 k][34]
    ull*   red = (ull*)(smraw + RED_OFF);            // [128 thr][17]

    const int tid = threadIdx.x;
    const int bi = blockIdx.x & 15;
    const int ci = blockIdx.x >> 4;
    const int b0 = bi * 32;
    const int n0 = ci * 128;
    const int wid = tid >> 5;                        // 0..7
    const int lane = tid & 31;
    const int wrp = wid & 3;                         // batch group
    const int kh = wid >> 2;                         // k half
    const int bwl = wrp * 8;
    const int bw = b0 + bwl;
    const int g0 = n0 + lane * 4;
    const int cellG = ci * 32 + lane;
    const int st_r = tid & 31;
    const int st_q = tid >> 5;

    for (int i = tid; i < 8192; i += 256) {
        int c = i & 127, kq = (i >> 7) << 2;
        float4 v = *(const float4*)&g_Whhr[(n0 + c) * DD + kq];
        ws[(kq + 0) * 128 + c] = v.x;
        ws[(kq + 1) * 128 + c] = v.y;
        ws[(kq + 2) * 128 + c] = v.z;
        ws[(kq + 3) * 128 + c] = v.w;
    }

    int sl[8];
    float cst[8];
#pragma unroll
    for (int j = 0; j < 8; j++) {
        sl[j] = g_seqlen[bw + j];
        cst[j] = 0.0f;
    }

    ull Gp[16];
#pragma unroll
    for (int i = 0; i < 16; i++) Gp[i] = 0ULL;
    if (wid < 4) {
        float gv[2][4];
#pragma unroll
        for (int bp = 0; bp < 4; bp++) {
#pragma unroll
            for (int e = 0; e < 2; e++) {
                int b = bw + bp * 2 + e;
                int4 id = __ldg(&g_idx[b]);
                float4 v1 = *(const float4*)&g_locC[(size_t)id.x * NG + g0];
                float4 v2 = *(const float4*)&g_userC[(size_t)id.y * NG + g0];
                float4 v3 = *(const float4*)&g_hwC[(size_t)id.z * NG + g0];
                gv[e][0] = v1.x + v2.x + v3.x;
                gv[e][1] = v1.y + v2.y + v3.y;
                gv[e][2] = v1.z + v2.z + v3.z;
                gv[e][3] = v1.w + v2.w + v3.w;
            }
#pragma unroll
            for (int g = 0; g < 4; g++)
                Gp[bp * 4 + g] = pk2(gv[0][g], gv[1][g]);
        }
    }
    __syncthreads();

    for (int t = 0; t < SS; t++) {
        ull acc[16];
#pragma unroll
        for (int i = 0; i < 16; i++) acc[i] = Gp[i];

        if (t > 0) {
            poll_cnt(&g_bar[(t - 1) * 16 + bi]);
            const float* hsrc = g_h[t & 1] + (size_t)(b0 + st_r) * DD;
#pragma unroll
            for (int it = 0; it < 8; it++) {
                int k4 = (st_q + it * 8) << 2;
                float4 v = __ldcg((const float4*)(hsrc + k4));
                hs[(k4 + 0) * 34 + st_r] = v.x;
                hs[(k4 + 1) * 34 + st_r] = v.y;
                hs[(k4 + 2) * 34 + st_r] = v.z;
                hs[(k4 + 3) * 34 + st_r] = v.w;
            }
            __syncthreads();

            const float* wp = ws + lane * 4 + (kh << 14);
            const float* hb = hs + bwl + kh * 128 * 34;
#pragma unroll 4
            for (int kk = 0; kk < 128; kk++) {
                float4 w4 = *(const float4*)(wp + (kk << 7));
                ull W0 = pk2(w4.x, w4.x), W1 = pk2(w4.y, w4.y);
                ull W2 = pk2(w4.z, w4.z), W3 = pk2(w4.w, w4.w);
                const ull* hk = (const ull*)(hb + kk * 34);
                ull h0 = hk[0], h1 = hk[1], h2 = hk[2], h3 = hk[3];
                fma2(acc[0], h0, W0);  fma2(acc[1], h0, W1);
                fma2(acc[2], h0, W2);  fma2(acc[3], h0, W3);
                fma2(acc[4], h1, W0);  fma2(acc[5], h1, W1);
                fma2(acc[6], h1, W2);  fma2(acc[7], h1, W3);
                fma2(acc[8], h2, W0);  fma2(acc[9], h2, W1);
                fma2(acc[10], h2, W2); fma2(acc[11], h2, W3);
                fma2(acc[12], h3, W0); fma2(acc[13], h3, W1);
                fma2(acc[14], h3, W2); fma2(acc[15], h3, W3);
            }

            if (wid >= 4) {
                ull* d = red + (size_t)(tid - 128) * 17;
#pragma unroll
                for (int i = 0; i < 16; i++) d[i] = acc[i];
            }
            __syncthreads();
            if (wid < 4) {
                const ull* s = red + (size_t)tid * 17;
#pragma unroll
                for (int i = 0; i < 16; i++) add2(acc[i], s[i]);
            }
        }

        if (wid < 4) {
            float hn[8];
#pragma unroll
            for (int bp = 0; bp < 4; bp++) {
                float2 gi = upk(acc[bp * 4 + 0]);
                float2 gf = upk(acc[bp * 4 + 1]);
                float2 gg = upk(acc[bp * 4 + 2]);
                float2 go = upk(acc[bp * 4 + 3]);
                int b0e = bp * 2, b1e = bp * 2 + 1;
                float cn0 = sigm(gf.x) * cst[b0e] + sigm(gi.x) * tanh_(gg.x);
                hn[b0e] = sigm(go.x) * tanh_(cn0);
                cst[b0e] = cn0;
                float cn1 = sigm(gf.y) * cst[b1e] + sigm(gi.y) * tanh_(gg.y);
                hn[b1e] = sigm(go.y) * tanh_(cn1);
                cst[b1e] = cn1;
                if (t == sl[b0e]) g_context[(bw + b0e) * DD + cellG] = hn[b0e];
                if (t == sl[b1e]) g_context[(bw + b1e) * DD + cellG] = hn[b1e];
            }
            if (t < SS - 1) {
                float* h_out = g_h[(t + 1) & 1];
#pragma unroll
                for (int j = 0; j < 8; j++)
                    __stcg(&h_out[(bw + j) * DD + cellG], hn[j]);
            }
        }

        if (t < SS - 1) {
            __threadfence();
            __syncthreads();
            if (tid == 0) atomicAdd(&g_bar[t * 16 + bi], 1);

            if (wid < 4) {
                float gv[2][4];
#pragma unroll
                for (int bp = 0; bp < 4; bp++) {
#pragma unroll
                    for (int e = 0; e < 2; e++) {
                        int b = bw + bp * 2 + e;
                        int4 id = __ldg(&g_idx[(t + 1) * BB + b]);
                        float4 v1 = *(const float4*)&g_locC[(size_t)id.x * NG + g0];
                        float4 v2 = *(const float4*)&g_userC[(size_t)id.y * NG + g0];
                        float4 v3 = *(const float4*)&g_hwC[(size_t)id.z * NG + g0];
                        gv[e][0] = v1.x + v2.x + v3.x;
                        gv[e][1] = v1.y + v2.y + v3.y;
                        gv[e][2] = v1.z + v2.z + v3.z;
                        gv[e][3] = v1.w + v2.w + v3.w;
                    }
#pragma unroll
                    for (int g = 0; g < 4; g++)
                        Gp[bp * 4 + g] = pk2(gv[0][g], gv[1][g]);
                }
            }
        }
    }
}

// ---------------- context MLP: hidden1 = gelu(ctx @ np_W1^T + b1); mix ------
__global__ void ctx_mlp(const float* __restrict__ np_W1, const float* __restrict__ np_b1,
                        const float* __restrict__ mx_W, const float* __restrict__ mx_b) {
    int b = blockIdx.x, tid = threadIdx.x;
    __shared__ float ctx[DD];
    __shared__ float red[DD];
    ctx[tid] = g_context[b * DD + tid];
    __syncthreads();
    float accv = np_b1[tid];
    const float* w = np_W1 + (size_t)tid * DD;
#pragma unroll 4
    for (int k = 0; k < DD; k++) accv += ctx[k] * w[k];
    g_hidden1[b * DD + tid] = geluf(accv);

    red[tid] = ctx[tid] * mx_W[tid];
    __syncthreads();
    for (int off = 128; off > 0; off >>= 1) {
        if (tid < off) red[tid] += red[tid + off];
        __syncthreads();
    }
    if (tid == 0) g_mix[b] = 1.0f / (1.0f + expf(-(red[0] + mx_b[0]))) * 0.9f + 0.05f;
}

// ---------------- recent-location scoring + dedup ----------------
__global__ void recent_kernel(const int* __restrict__ locations,
                              const int* __restrict__ start_mins,
                              const float* __restrict__ loc_table,
                              const float* __restrict__ sc_W1,
                              const float* __restrict__ sc_b1,
                              const float* __restrict__ sc_W2,
                              const float* __restrict__ sc_b2) {
    int b = blockIdx.x, tid = threadIdx.x;   // 128 threads
    __shared__ int rloc[5];
    __shared__ float td[5];
    __shared__ int val[5];
    __shared__ float hid[5][128];
    if (tid < 5) {
        int sl = g_seqlen[b];
        int idx = sl - tid;
        val[tid] = (idx >= 0);
        int ic = idx < 0 ? 0 : idx;
        rloc[tid] = locations[b * SS + ic];
        int ct = start_mins[b * SS + sl];
        td[tid] = (float)(ct - start_mins[b * SS + ic]) / 1440.0f;
    }
    __syncthreads();
    for (int j = 0; j < 5; j++) {
        const float* lt = loc_table + (size_t)rloc[j] * DD;
        const float* w = sc_W1 + (size_t)tid * 258;
        float a = sc_b1[tid] + td[j] * w[256] + (float)j * w[257];
#pragma unroll 4
        for (int k = 0; k < DD; k++) a += lt[k] * w[k];
        hid[j][tid] = geluf(a);
    }
    __syncthreads();
    if (tid < 5) {
        float sc = sc_b2[0];
        for (int k = 0; k < 128; k++) sc += hid[tid][k] * sc_W2[k];
        int keep = val[tid];
        for (int jp = 0; jp < tid; jp++)
            if (val[jp] && rloc[jp] == rloc[tid]) keep = 0;
        g_recloc[b * 5 + tid] = keep ? rloc[tid] : -1;
        g_recscore[b * 5 + tid] = sc;
    }
}

// ---------------- fixup: overwrite kept recent locations ----------------
__global__ void fixup_kernel(const float* __restrict__ np_W2,
                             const float* __restrict__ np_b2,
                             float* __restrict__ out) {
    int b = blockIdx.x, tid = threadIdx.x;   // 256 threads
    __shared__ float h1[DD];
    __shared__ float red[DD];
    h1[tid] = g_hidden1[b * DD + tid];
    __syncthreads();
    float mm = g_mix[b];
    for (int j = 0; j < 5; j++) {
        int l = g_recloc[b * 5 + j];
        if (l < 0) continue;
        red[tid] = h1[tid] * np_W2[(size_t)l * DD + tid];
        __syncthreads();
        for (int off = 128; off > 0; off >>= 1) {
            if (tid < off) red[tid] += red[tid + off];
            __syncthreads();
        }
        if (tid == 0)
            out[(size_t)b * NUM_LOC + l] =
                mm * g_recscore[b * 5 + j] + (1.0f - mm) * (red[0] + np_b2[l]);
        __syncthreads();
    }
}

// ---------------- launch ----------------
extern "C" void kernel_launch(void* const* d_in, const int* in_sizes, int n_in,
                              void* d_out, int out_size) {
    const int* locations   = (const int*)d_in[0];
    const int* users       = (const int*)d_in[1];
    const int* weekdays    = (const int*)d_in[2];
    const int* start_mins  = (const int*)d_in[3];
    const void* mask       = d_in[4];
    const float* loc_table  = (const float*)d_in[5];
    const float* user_table = (const float*)d_in[6];
    const float* hour_table = (const float*)d_in[7];
    const float* wd_table   = (const float*)d_in[8];
    const float* W_ih = (const float*)d_in[9];
    const float* W_hh = (const float*)d_in[10];
    const float* b_ih = (const float*)d_in[11];
    const float* b_hh = (const float*)d_in[12];
    const float* sc_W1 = (const float*)d_in[13];
    const float* sc_b1 = (const float*)d_in[14];
    const float* sc_W2 = (const float*)d_in[15];
    const float* sc_b2 = (const float*)d_in[16];
    const float* np_W1 = (const float*)d_in[17];
    const float* np_b1 = (const float*)d_in[18];
    const float* np_W2 = (const float*)d_in[19];
    const float* np_b2 = (const float*)d_in[20];
    const float* mx_W = (const float*)d_in[21];
    const float* mx_b = (const float*)d_in[22];
    float* out = (float*)d_out;

    detect_mask<<<1, 256>>>((const unsigned char*)mask);
    seqlen_kernel<<<2, 256>>>(mask);
    reorder_kernel<<<1024, 256>>>(W_hh, b_ih, b_hh);
    build_idx<<<SS, 512>>>(locations, users, weekdays, start_mins);

    gemm_tf32<<<dim3(391, 8), 256>>>(loc_table, NUM_LOC, 256, W_ih, 448, 0, 256, NG, 0, nullptr, nullptr);
    gemm_tf32<<<dim3(79, 8), 256>>>(user_table, NUM_USERS, 64, W_ih, 448, 256, 64, NG, 1, nullptr, nullptr);
    gemm_small<<<dim3(1, 8), 256>>>(hour_table, 25, 64, W_ih, 448, 320, 64, 2);
    gemm_small<<<dim3(1, 8), 256>>>(wd_table, 8, 64, W_ih, 448, 384, 64, 3);
    build_hw<<<200, 256>>>();

    cudaFuncSetAttribute(lstm_persistent, cudaFuncAttributeMaxDynamicSharedMemorySize, LSTM_SMEM);
    lstm_persistent<<<128, 256, LSTM_SMEM>>>();

    ctx_mlp<<<512, 256>>>(np_W1, np_b1, mx_W, mx_b);
    recent_kernel<<<512, 128>>>(locations, start_mins, loc_table,
                                sc_W1, sc_b1, sc_W2, sc_b2);
    gemm_tf32<<<dim3(4, 391), 256>>>(nullptr, BB, 256, np_W2, 256, 0, 256, NUM_LOC, 4, np_b2, out);
    fixup_kernel<<<512, 256>>>(np_W2, np_b2, out);
}

// round 17
// speedup vs baseline: 1.6568x; 1.4205x over previous
#include <cuda_runtime.h>
#include <stdint.h>
#include <math.h>

#define BB 512
#define SS 256
#define NUM_LOC 50000
#define NUM_USERS 10000
#define DD 256
#define NG 1024        // 4*D gate dim (gate-interleaved n' = 4*cell + gate)
#define NEGV -1000000000.0f

// ---------------- device scratch (no cudaMalloc allowed) ----------------
__device__ float g_locC[(size_t)NUM_LOC * NG];     // 204.8 MB (bias folded in)
__device__ float g_userC[(size_t)NUM_USERS * NG];  // 41 MB
__device__ float g_hourC[25 * NG];
__device__ float g_wdC[8 * NG];
__device__ float g_hwC[200 * NG];                  // combined hour*8+wd table
__device__ float g_biasr[NG];
__device__ float g_Whhr[NG * DD];                  // gate-interleaved W_hh
__device__ float g_h[2][BB * DD];                  // double-buffered hidden
__device__ float g_context[BB * DD];
__device__ int   g_seqlen[BB];
__device__ float g_hidden1[BB * DD];
__device__ float g_mix[BB];
__device__ int   g_recloc[BB * 5];
__device__ float g_recscore[BB * 5];
__device__ int   g_maskflag[1];
__device__ int4  g_idx[SS * BB];                   // per (t, b): loc, user, hr*8+wd
__device__ int   g_bar[SS * 16];                   // per-step, per-batch-group counters

typedef unsigned long long ull;
typedef unsigned int u32;
__device__ __forceinline__ ull pk2(float x, float y) {
    ull r; asm("mov.b64 %0, {%1, %2};" : "=l"(r) : "f"(x), "f"(y)); return r;
}
__device__ __forceinline__ float2 upk(ull v) {
    float2 r; asm("mov.b64 {%0, %1}, %2;" : "=f"(r.x), "=f"(r.y) : "l"(v)); return r;
}
__device__ __forceinline__ void poll_cnt(const int* p) {
    int v;
    do {
        asm volatile("ld.acquire.gpu.global.b32 %0, [%1];" : "=r"(v) : "l"(p));
    } while (v < 8);
}
__device__ __forceinline__ u32 tf32c(float x) {
    u32 r; asm("cvt.rna.tf32.f32 %0, %1;" : "=r"(r) : "f"(x)); return r;
}
#define MMA_TF32(d, a, b) \
    asm("mma.sync.aligned.m16n8k8.row.col.f32.tf32.tf32.f32 " \
        "{%0,%1,%2,%3}, {%4,%5,%6,%7}, {%8,%9}, {%0,%1,%2,%3};" \
        : "+f"((d)[0]), "+f"((d)[1]), "+f"((d)[2]), "+f"((d)[3]) \
        : "r"((a)[0]), "r"((a)[1]), "r"((a)[2]), "r"((a)[3]), \
          "r"((b)[0]), "r"((b)[1]))

__device__ __forceinline__ float geluf(float x) {
    return 0.5f * x * (1.0f + erff(x * 0.70710678118654752f));
}
__device__ __forceinline__ float sigm(float x) { return 1.0f / (1.0f + __expf(-x)); }
__device__ __forceinline__ float tanh_(float x) {
    return 1.0f - 2.0f / (__expf(2.0f * x) + 1.0f);
}

// ---------------- mask dtype detection ----------------
__global__ void detect_mask(const unsigned char* mask) {
    __shared__ int s;
    if (threadIdx.x == 0) s = 0;
    __syncthreads();
    int f = 0;
    for (int i = threadIdx.x * 4 + 1; i < BB * SS; i += blockDim.x * 4)
        if (mask[i]) f = 1;
    if (f) atomicOr(&s, 1);
    __syncthreads();
    if (threadIdx.x == 0) g_maskflag[0] = s;
}

__global__ void seqlen_kernel(const void* mask) {
    int b = blockIdx.x * blockDim.x + threadIdx.x;
    if (b >= BB) return;
    int flag = g_maskflag[0];
    int cnt = 0;
    if (flag) {
        const unsigned char* m = (const unsigned char*)mask;
        for (int s = 0; s < SS; s++) cnt += (m[b * SS + s] != 0);
    } else {
        const int* m = (const int*)mask;
        for (int s = 0; s < SS; s++) cnt += (m[b * SS + s] != 0);
    }
    g_seqlen[b] = cnt - 1;
}

// gate-interleave W_hh and biases; zero barrier counters (every replay)
__global__ void reorder_kernel(const float* __restrict__ W_hh,
                               const float* __restrict__ b_ih,
                               const float* __restrict__ b_hh) {
    int np = blockIdx.x;                     // 0..1023
    int row = ((np & 3) << 8) + (np >> 2);
    g_Whhr[np * DD + threadIdx.x] = W_hh[row * DD + threadIdx.x];
    if (threadIdx.x == 0) g_biasr[np] = b_ih[row] + b_hh[row];
    if (np < 16) g_bar[np * 256 + threadIdx.x] = 0;
}

// transpose indices to [t][b] with hour/wd combined
__global__ void build_idx(const int* __restrict__ locs, const int* __restrict__ usrs,
                          const int* __restrict__ wds, const int* __restrict__ sms) {
    int t = blockIdx.x, b = threadIdx.x;     // grid SS, block 512
    int4 v;
    v.x = locs[b * SS + t];
    v.y = usrs[b * SS + t];
    int hr = sms[b * SS + t] / 60;
    if (hr > 24) hr = 24;
    v.z = hr * 8 + wds[b * SS + t];
    v.w = 0;
    g_idx[t * BB + b] = v;
}

// combined hour+weekday contribution table (after contrib GEMMs)
__global__ void build_hw() {
    int r = blockIdx.x;                      // 0..199
    int c = threadIdx.x * 4;                 // 256 threads
    float4 a = *(const float4*)&g_hourC[(r >> 3) * NG + c];
    float4 b = *(const float4*)&g_wdC[(r & 7) * NG + c];
    float4 o = make_float4(a.x + b.x, a.y + b.y, a.z + b.z, a.w + b.w);
    *(float4*)&g_hwC[r * NG + c] = o;
}

// ---------------- tf32 tensor-core GEMM: 128x128 tile, 8 warps (2x4) -------
__global__ void __launch_bounds__(256, 2)
gemm_tf32(const float* __restrict__ A, int M, int lda,
          const float* __restrict__ W, int ldw, int k0, int K,
          int N, int mode, const float* __restrict__ bias2,
          float* __restrict__ out) {
    __shared__ u32 As[32][136];
    __shared__ u32 Ws[32][136];
    if (mode == 4) A = g_hidden1;

    const int m0 = blockIdx.x * 128;
    const int n0 = blockIdx.y * 128;
    const int tid = threadIdx.x;
    const int wid = tid >> 5, lane = tid & 31;
    const int g = lane >> 2, tq = lane & 3;
    const int wm = wid >> 2, wn = wid & 3;
    const int mb = wm * 64, nb = wn * 32;

    const int sr = tid >> 1;
    const int sk = (tid & 1) * 16;

    const bool aok = (m0 + sr) < M;
    const float* ap = A + (size_t)(aok ? (m0 + sr) : 0) * lda;
    int wcol = n0 + sr;
    bool wok;
    const float* wp;
    if (mode < 4) {
        int wr = ((wcol & 3) << 8) + (wcol >> 2);
        wp = W + (size_t)wr * ldw + k0;
        wok = true;
    } else {
        wok = wcol < N;
        wp = W + (size_t)(wok ? wcol : 0) * ldw;
    }

    float acc[4][4][4];
#pragma unroll
    for (int mt = 0; mt < 4; mt++)
#pragma unroll
        for (int nt = 0; nt < 4; nt++)
#pragma unroll
            for (int c = 0; c < 4; c++) acc[mt][nt][c] = 0.0f;

    const float4 Z = make_float4(0.f, 0.f, 0.f, 0.f);

    for (int kk = 0; kk < K; kk += 32) {
#pragma unroll
        for (int i = 0; i < 4; i++) {
            float4 va = aok ? *(const float4*)(ap + kk + sk + i * 4) : Z;
            float4 vw = wok ? *(const float4*)(wp + kk + sk + i * 4) : Z;
            int kb = sk + i * 4;
            As[kb + 0][sr] = tf32c(va.x);
            As[kb + 1][sr] = tf32c(va.y);
            As[kb + 2][sr] = tf32c(va.z);
            As[kb + 3][sr] = tf32c(va.w);
            Ws[kb + 0][sr] = tf32c(vw.x);
            Ws[kb + 1][sr] = tf32c(vw.y);
            Ws[kb + 2][sr] = tf32c(vw.z);
            Ws[kb + 3][sr] = tf32c(vw.w);
        }
        __syncthreads();

#pragma unroll
        for (int kt = 0; kt < 4; kt++) {
            u32 a[4][4], b[4][2];
            const int kA = kt * 8 + tq;
#pragma unroll
            for (int mt = 0; mt < 4; mt++) {
                int mr = mb + mt * 16 + g;
                a[mt][0] = As[kA][mr];
                a[mt][1] = As[kA][mr + 8];
                a[mt][2] = As[kA + 4][mr];
                a[mt][3] = As[kA + 4][mr + 8];
            }
#pragma unroll
            for (int nt = 0; nt < 4; nt++) {
                int nc = nb + nt * 8 + g;
                b[nt][0] = Ws[kA][nc];
                b[nt][1] = Ws[kA + 4][nc];
            }
#pragma unroll
            for (int mt = 0; mt < 4; mt++)
#pragma unroll
                for (int nt = 0; nt < 4; nt++)
                    MMA_TF32(acc[mt][nt], a[mt], b[nt]);
        }
        __syncthreads();
    }

    float* C = (mode == 0) ? g_locC : (mode == 1) ? g_userC : out;
#pragma unroll
    for (int mt = 0; mt < 4; mt++) {
        int row0 = m0 + mb + mt * 16 + g;
        int row1 = row0 + 8;
#pragma unroll
        for (int nt = 0; nt < 4; nt++) {
            int col = n0 + nb + nt * 8 + 2 * tq;
            if (mode < 4) {
                float bx = 0.f, by = 0.f;
                if (mode == 0) {
                    float2 bv = *(const float2*)&g_biasr[col];
                    bx = bv.x; by = bv.y;
                }
                if (row0 < M)
                    *(float2*)&C[(size_t)row0 * NG + col] =
                        make_float2(acc[mt][nt][0] + bx, acc[mt][nt][1] + by);
                if (row1 < M)
                    *(float2*)&C[(size_t)row1 * NG + col] =
                        make_float2(acc[mt][nt][2] + bx, acc[mt][nt][3] + by);
            } else {
                if (col < N) {
                    float2 b2 = *(const float2*)&bias2[col];
                    if (row0 < M) {
                        float mm = g_mix[row0];
                        float om = 1.0f - mm, base = mm * NEGV;
                        *(float2*)&C[(size_t)row0 * NUM_LOC + col] =
                            make_float2(base + om * (acc[mt][nt][0] + b2.x),
                                        base + om * (acc[mt][nt][1] + b2.y));
                    }
                    if (row1 < M) {
                        float mm = g_mix[row1];
                        float om = 1.0f - mm, base = mm * NEGV;
                        *(float2*)&C[(size_t)row1 * NUM_LOC + col] =
                            make_float2(base + om * (acc[mt][nt][2] + b2.x),
                                        base + om * (acc[mt][nt][3] + b2.y));
                    }
                }
            }
        }
    }
}

// ---------------- small fp32 GEMM for hour/wd tables (modes 2,3) -----------
__global__ void __launch_bounds__(256)
gemm_small(const float* __restrict__ A, int M, int lda,
           const float* __restrict__ W, int ldw, int k0, int K, int mode) {
    float* C = (mode == 2) ? g_hourC : g_wdC;
    const int n0 = blockIdx.y * 128;
    const int tid = threadIdx.x;
    const int nl = tid >> 1;
    const int mh = tid & 1;
    int wn = n0 + nl;
    int wr = ((wn & 3) << 8) + (wn >> 2);
    const float* wp = W + (size_t)wr * ldw + k0;
    for (int m = mh; m < M; m += 2) {
        float s = 0.f;
        const float* arow = A + (size_t)m * lda;
        for (int k = 0; k < K; k++) s += arow[k] * wp[k];
        C[(size_t)m * NG + n0 + nl] = s;
    }
}

// ---------------- persistent LSTM v10: tensor-core recurrent MMA -----------
// grid 128 CTAs, 256 thr. block (bi, ci): batch rows [bi*32,+32), gate cols
// [ci*128,+128). Per step: C[128 gates][32 batch] = W[128][256] x h[32][256]^T
// via m16n8k8 tf32. warp w = m-tile (16 gates), all 4 n-tiles, 32 k-tiles.
// W and h staged in SMEM as tf32, rows padded to 260 (=4 mod 32 -> all
// fragment LDS.32 conflict-free). Accumulators dumped to accsm[batch][132],
// pointwise re-tiled: thread = (cell, 4 batches), gates read as LDS.128.
// G (input contributions) gathered into gsm[batch][132], added in fp32.
#define WPAD 260
#define WS2_BYTES (128 * WPAD * 4)          // 133120
#define HS2_OFF   WS2_BYTES
#define HS2_BYTES (32 * WPAD * 4)           // 33280
#define ACC_OFF   (HS2_OFF + HS2_BYTES)
#define ACC_BYTES (32 * 132 * 4)            // 16896
#define GS_OFF    (ACC_OFF + ACC_BYTES)
#define LSTM_SMEM (GS_OFF + ACC_BYTES)      // 200192

__global__ void __launch_bounds__(256, 1)
lstm_persistent() {
    extern __shared__ char smraw[];
    u32*   wsT  = (u32*)smraw;                       // [128 gate][260] tf32
    u32*   hsT  = (u32*)(smraw + HS2_OFF);           // [32 batch][260] tf32
    float* accs = (float*)(smraw + ACC_OFF);         // [32 batch][132]
    float* gsm  = (float*)(smraw + GS_OFF);          // [32 batch][132]

    const int tid = threadIdx.x;
    const int bi = blockIdx.x & 15;
    const int ci = blockIdx.x >> 4;
    const int b0 = bi * 32;
    const int n0 = ci * 128;
    const int wid = tid >> 5, lane = tid & 31;
    const int g = lane >> 2, tq = lane & 3;

    // pointwise identity: thread = (cell, batch group)
    const int pcell = tid & 31;
    const int pbg = tid >> 5;                        // batches pbg*4..+3
    const int cellG = ci * 32 + pcell;

    // G-gather identity
    const int gb = tid >> 3;                         // batch 0..31
    const int gch = (tid & 7) * 16;                  // col chunk

    // stage W slice as tf32: wsT[c][k] = tf32(Whhr[(n0+c)*DD + k])
    for (int i = tid; i < 8192; i += 256) {
        int c = i & 127, kq = (i >> 7) << 2;
        float4 v = *(const float4*)&g_Whhr[(n0 + c) * DD + kq];
        uint4 o;
        o.x = tf32c(v.x); o.y = tf32c(v.y); o.z = tf32c(v.z); o.w = tf32c(v.w);
        *(uint4*)&wsT[c * WPAD + kq] = o;
    }
    // zero accsm (t=0 reads it)
    for (int i = tid; i < 32 * 132; i += 256) accs[i] = 0.0f;

    int sl[4];
    float cst[4];
#pragma unroll
    for (int j = 0; j < 4; j++) {
        sl[j] = g_seqlen[b0 + pbg * 4 + j];
        cst[j] = 0.0f;
    }

    // prefetch G for t=0 into gsm[batch][132]
    {
        int4 id = __ldg(&g_idx[b0 + gb]);
        const float* p1 = &g_locC[(size_t)id.x * NG + n0 + gch];
        const float* p2 = &g_userC[(size_t)id.y * NG + n0 + gch];
        const float* p3 = &g_hwC[(size_t)id.z * NG + n0 + gch];
#pragma unroll
        for (int q = 0; q < 4; q++) {
            float4 a = *(const float4*)(p1 + q * 4);
            float4 b = *(const float4*)(p2 + q * 4);
            float4 c = *(const float4*)(p3 + q * 4);
            *(float4*)&gsm[gb * 132 + gch + q * 4] =
                make_float4(a.x + b.x + c.x, a.y + b.y + c.y,
                            a.z + b.z + c.z, a.w + b.w + c.w);
        }
    }
    __syncthreads();

    const int st_r = tid >> 3;                       // staging batch row
    const int st_k = (tid & 7) * 4;                  // staging k base

    for (int t = 0; t < SS; t++) {
        if (t > 0) {
            poll_cnt(&g_bar[(t - 1) * 16 + bi]);
            // stage h -> hsT tf32
            const float* hsrc = g_h[t & 1] + (size_t)(b0 + st_r) * DD;
#pragma unroll
            for (int it = 0; it < 8; it++) {
                int k4 = st_k + it * 32;
                float4 v = __ldcg((const float4*)(hsrc + k4));
                uint4 o;
                o.x = tf32c(v.x); o.y = tf32c(v.y);
                o.z = tf32c(v.z); o.w = tf32c(v.w);
                *(uint4*)&hsT[st_r * WPAD + k4] = o;
            }
            __syncthreads();

            // MMA: warp wid covers gates [wid*16, +16), all 32 batches
            float acc[4][4];
#pragma unroll
            for (int nt = 0; nt < 4; nt++)
#pragma unroll
                for (int c = 0; c < 4; c++) acc[nt][c] = 0.0f;

            const u32* wa = wsT + (wid * 16 + g) * WPAD;
            const u32* wa8 = wa + 8 * WPAD;
#pragma unroll 8
            for (int kt = 0; kt < 32; kt++) {
                int kA = kt * 8 + tq;
                u32 a[4];
                a[0] = wa[kA];
                a[1] = wa8[kA];
                a[2] = wa[kA + 4];
                a[3] = wa8[kA + 4];
#pragma unroll
                for (int nt = 0; nt < 4; nt++) {
                    const u32* hb = hsT + (nt * 8 + g) * WPAD;
                    u32 b[2] = { hb[kA], hb[kA + 4] };
                    MMA_TF32(acc[nt], a, b);
                }
            }

            // dump: accs[batch][gatecol]
#pragma unroll
            for (int nt = 0; nt < 4; nt++) {
                int bq = nt * 8 + 2 * tq;
                int col = wid * 16 + g;
                accs[bq * 132 + col] = acc[nt][0];
                accs[(bq + 1) * 132 + col] = acc[nt][1];
                accs[bq * 132 + col + 8] = acc[nt][2];
                accs[(bq + 1) * 132 + col + 8] = acc[nt][3];
            }
            __syncthreads();
        }

        // pointwise: thread = (pcell, batches pbg*4..+3)
        float hn[4];
#pragma unroll
        for (int j = 0; j < 4; j++) {
            int b = pbg * 4 + j;
            float4 av = *(const float4*)&accs[b * 132 + 4 * pcell];
            float4 gv = *(const float4*)&gsm[b * 132 + 4 * pcell];
            float ii = av.x + gv.x, ff = av.y + gv.y;
            float gg = av.z + gv.z, oo = av.w + gv.w;
            float cn = sigm(ff) * cst[j] + sigm(ii) * tanh_(gg);
            hn[j] = sigm(oo) * tanh_(cn);
            cst[j] = cn;
            if (t == sl[j]) g_context[(size_t)(b0 + b) * DD + cellG] = hn[j];
        }

        if (t < SS - 1) {
            float* hout = g_h[(t + 1) & 1];
#pragma unroll
            for (int j = 0; j < 4; j++)
                __stcg(&hout[(size_t)(b0 + pbg * 4 + j) * DD + cellG], hn[j]);
            __threadfence();
            __syncthreads();
            if (tid == 0) atomicAdd(&g_bar[t * 16 + bi], 1);

            // prefetch G for t+1 (gsm reads of step t completed at barrier)
            int4 id = __ldg(&g_idx[(t + 1) * BB + b0 + gb]);
            const float* p1 = &g_locC[(size_t)id.x * NG + n0 + gch];
            const float* p2 = &g_userC[(size_t)id.y * NG + n0 + gch];
            const float* p3 = &g_hwC[(size_t)id.z * NG + n0 + gch];
#pragma unroll
            for (int q = 0; q < 4; q++) {
                float4 a = *(const float4*)(p1 + q * 4);
                float4 b = *(const float4*)(p2 + q * 4);
                float4 c = *(const float4*)(p3 + q * 4);
                *(float4*)&gsm[gb * 132 + gch + q * 4] =
                    make_float4(a.x + b.x + c.x, a.y + b.y + c.y,
                                a.z + b.z + c.z, a.w + b.w + c.w);
            }
        }
    }
}

// ---------------- context MLP: hidden1 = gelu(ctx @ np_W1^T + b1); mix ------
__global__ void ctx_mlp(const float* __restrict__ np_W1, const float* __restrict__ np_b1,
                        const float* __restrict__ mx_W, const float* __restrict__ mx_b) {
    int b = blockIdx.x, tid = threadIdx.x;
    __shared__ float ctx[DD];
    __shared__ float red[DD];
    ctx[tid] = g_context[b * DD + tid];
    __syncthreads();
    float accv = np_b1[tid];
    const float* w = np_W1 + (size_t)tid * DD;
#pragma unroll 4
    for (int k = 0; k < DD; k++) accv += ctx[k] * w[k];
    g_hidden1[b * DD + tid] = geluf(accv);

    red[tid] = ctx[tid] * mx_W[tid];
    __syncthreads();
    for (int off = 128; off > 0; off >>= 1) {
        if (tid < off) red[tid] += red[tid + off];
        __syncthreads();
    }
    if (tid == 0) g_mix[b] = 1.0f / (1.0f + expf(-(red[0] + mx_b[0]))) * 0.9f + 0.05f;
}

// ---------------- recent-location scoring + dedup ----------------
__global__ void recent_kernel(const int* __restrict__ locations,
                              const int* __restrict__ start_mins,
                              const float* __restrict__ loc_table,
                              const float* __restrict__ sc_W1,
                              const float* __restrict__ sc_b1,
                              const float* __restrict__ sc_W2,
                              const float* __restrict__ sc_b2) {
    int b = blockIdx.x, tid = threadIdx.x;   // 128 threads
    __shared__ int rloc[5];
    __shared__ float td[5];
    __shared__ int val[5];
    __shared__ float hid[5][128];
    if (tid < 5) {
        int sl = g_seqlen[b];
        int idx = sl - tid;
        val[tid] = (idx >= 0);
        int ic = idx < 0 ? 0 : idx;
        rloc[tid] = locations[b * SS + ic];
        int ct = start_mins[b * SS + sl];
        td[tid] = (float)(ct - start_mins[b * SS + ic]) / 1440.0f;
    }
    __syncthreads();
    for (int j = 0; j < 5; j++) {
        const float* lt = loc_table + (size_t)rloc[j] * DD;
        const float* w = sc_W1 + (size_t)tid * 258;
        float a = sc_b1[tid] + td[j] * w[256] + (float)j * w[257];
#pragma unroll 4
        for (int k = 0; k < DD; k++) a += lt[k] * w[k];
        hid[j][tid] = geluf(a);
    }
    __syncthreads();
    if (tid < 5) {
        float sc = sc_b2[0];
        for (int k = 0; k < 128; k++) sc += hid[tid][k] * sc_W2[k];
        int keep = val[tid];
        for (int jp = 0; jp < tid; jp++)
            if (val[jp] && rloc[jp] == rloc[tid]) keep = 0;
        g_recloc[b * 5 + tid] = keep ? rloc[tid] : -1;
        g_recscore[b * 5 + tid] = sc;
    }
}

// ---------------- fixup: overwrite kept recent locations ----------------
__global__ void fixup_kernel(const float* __restrict__ np_W2,
                             const float* __restrict__ np_b2,
                             float* __restrict__ out) {
    int b = blockIdx.x, tid = threadIdx.x;   // 256 threads
    __shared__ float h1[DD];
    __shared__ float red[DD];
    h1[tid] = g_hidden1[b * DD + tid];
    __syncthreads();
    float mm = g_mix[b];
    for (int j = 0; j < 5; j++) {
        int l = g_recloc[b * 5 + j];
        if (l < 0) continue;
        red[tid] = h1[tid] * np_W2[(size_t)l * DD + tid];
        __syncthreads();
        for (int off = 128; off > 0; off >>= 1) {
            if (tid < off) red[tid] += red[tid + off];
            __syncthreads();
        }
        if (tid == 0)
            out[(size_t)b * NUM_LOC + l] =
                mm * g_recscore[b * 5 + j] + (1.0f - mm) * (red[0] + np_b2[l]);
        __syncthreads();
    }
}

// ---------------- launch ----------------
extern "C" void kernel_launch(void* const* d_in, const int* in_sizes, int n_in,
                              void* d_out, int out_size) {
    const int* locations   = (const int*)d_in[0];
    const int* users       = (const int*)d_in[1];
    const int* weekdays    = (const int*)d_in[2];
    const int* start_mins  = (const int*)d_in[3];
    const void* mask       = d_in[4];
    const float* loc_table  = (const float*)d_in[5];
    const float* user_table = (const float*)d_in[6];
    const float* hour_table = (const float*)d_in[7];
    const float* wd_table   = (const float*)d_in[8];
    const float* W_ih = (const float*)d_in[9];
    const float* W_hh = (const float*)d_in[10];
    const float* b_ih = (const float*)d_in[11];
    const float* b_hh = (const float*)d_in[12];
    const float* sc_W1 = (const float*)d_in[13];
    const float* sc_b1 = (const float*)d_in[14];
    const float* sc_W2 = (const float*)d_in[15];
    const float* sc_b2 = (const float*)d_in[16];
    const float* np_W1 = (const float*)d_in[17];
    const float* np_b1 = (const float*)d_in[18];
    const float* np_W2 = (const float*)d_in[19];
    const float* np_b2 = (const float*)d_in[20];
    const float* mx_W = (const float*)d_in[21];
    const float* mx_b = (const float*)d_in[22];
    float* out = (float*)d_out;

    detect_mask<<<1, 256>>>((const unsigned char*)mask);
    seqlen_kernel<<<2, 256>>>(mask);
    reorder_kernel<<<1024, 256>>>(W_hh, b_ih, b_hh);
    build_idx<<<SS, 512>>>(locations, users, weekdays, start_mins);

    gemm_tf32<<<dim3(391, 8), 256>>>(loc_table, NUM_LOC, 256, W_ih, 448, 0, 256, NG, 0, nullptr, nullptr);
    gemm_tf32<<<dim3(79, 8), 256>>>(user_table, NUM_USERS, 64, W_ih, 448, 256, 64, NG, 1, nullptr, nullptr);
    gemm_small<<<dim3(1, 8), 256>>>(hour_table, 25, 64, W_ih, 448, 320, 64, 2);
    gemm_small<<<dim3(1, 8), 256>>>(wd_table, 8, 64, W_ih, 448, 384, 64, 3);
    build_hw<<<200, 256>>>();

    cudaFuncSetAttribute(lstm_persistent, cudaFuncAttributeMaxDynamicSharedMemorySize, LSTM_SMEM);
    lstm_persistent<<<128, 256, LSTM_SMEM>>>();

    ctx_mlp<<<512, 256>>>(np_W1, np_b1, mx_W, mx_b);
    recent_kernel<<<512, 128>>>(locations, start_mins, loc_table,
                                sc_W1, sc_b1, sc_W2, sc_b2);
    gemm_tf32<<<dim3(4, 391), 256>>>(nullptr, BB, 256, np_W2, 256, 0, 256, NUM_LOC, 4, np_b2, out);
    fixup_kernel<<<512, 256>>>(np_W2, np_b2, out);
}